// round 9
// baseline (speedup 1.0000x reference)
#include <cuda_runtime.h>
#include <cuda_bf16.h>
#include <mma.h>
#include <math.h>
#include <stdint.h>

using namespace nvcuda;

// 0: x [1024,2560]  1: h [1024,2560,16]  2: W_dt_low [160,2560]  3: W_dt [2560,160]
// 4: b_dt [2560]    5: W_B [16,2560]     6: W_C [16,2560]        7: A_log [2560,16]
// 8: D [2560]       out: y [1024,2560]   all f32

#define B_SZ    1024
#define DIN     2560
#define DST     16
#define DTR     160
#define NPROJ   192
#define KPAD    192
#define SPLITK  8
#define KSPLIT  (DIN / SPLITK)   // 320
#define KC      32
#define PADK    40

// ---------------- device scratch ----------------
__device__ __align__(16) __nv_bfloat16 g_xh[B_SZ * DIN], g_xl[B_SZ * DIN];
__device__ __align__(16) __nv_bfloat16 g_w1h[NPROJ * DIN], g_w1l[NPROJ * DIN];
__device__ __align__(16) __nv_bfloat16 g_w2h[DIN * KPAD], g_w2l[DIN * KPAD];
__device__ __align__(16) __nv_bfloat16 g_ph[B_SZ * KPAD], g_pl[B_SZ * KPAD];
__device__ __align__(16) float g_partial[SPLITK * B_SZ * NPROJ];
__device__ __align__(16) float g_proj[B_SZ * NPROJ];
__device__ __align__(16) float g_dt[B_SZ * DIN];
__device__ __align__(16) float g_A2[DIN * DST];

// ---------------- helpers ----------------
__device__ __forceinline__ void split2(float v, __nv_bfloat16& hi, __nv_bfloat16& lo) {
    hi = __float2bfloat16(v);
    lo = __float2bfloat16(v - __bfloat162float(hi));
}
__device__ __forceinline__ void split_store4(float4 v, __nv_bfloat16* ph, __nv_bfloat16* pl) {
    __nv_bfloat16 h0, h1, h2, h3, l0, l1, l2, l3;
    split2(v.x, h0, l0); split2(v.y, h1, l1); split2(v.z, h2, l2); split2(v.w, h3, l3);
    reinterpret_cast<__nv_bfloat162*>(ph)[0] = __nv_bfloat162(h0, h1);
    reinterpret_cast<__nv_bfloat162*>(ph)[1] = __nv_bfloat162(h2, h3);
    reinterpret_cast<__nv_bfloat162*>(pl)[0] = __nv_bfloat162(l0, l1);
    reinterpret_cast<__nv_bfloat162*>(pl)[1] = __nv_bfloat162(l2, l3);
}
__device__ __forceinline__ void cp16(void* sdst, const void* gsrc) {
    asm volatile("cp.async.cg.shared.global [%0], [%1], 16;"
        :: "r"((uint32_t)__cvta_generic_to_shared(sdst)), "l"(gsrc));
}
#define CP_COMMIT() asm volatile("cp.async.commit_group;" ::: "memory")
#define CP_WAIT(N)  asm volatile("cp.async.wait_group %0;" :: "n"(N) : "memory")

// ---------------- fused prep ----------------
#define PREP_BLOCKS 3560
__global__ __launch_bounds__(256) void prep_all(const float* __restrict__ x,
                                                const float* __restrict__ wdtlow,
                                                const float* __restrict__ wb,
                                                const float* __restrict__ wc,
                                                const float* __restrict__ wdt,
                                                const float* __restrict__ alog) {
    const int bid = blockIdx.x;
    const int tid = threadIdx.x;
    if (bid < 2560) {
        int i = bid * 256 + tid;
        float4 v = reinterpret_cast<const float4*>(x)[i];
        split_store4(v, g_xh + i * 4, g_xl + i * 4);
    } else if (bid < 3040) {
        int i = (bid - 2560) * 256 + tid;
        int n = i / (DIN / 4);
        int j = i % (DIN / 4);
        const float* row = (n < DTR) ? wdtlow + (size_t)n * DIN
                         : (n < DTR + DST) ? wb + (size_t)(n - DTR) * DIN
                         : wc + (size_t)(n - DTR - DST) * DIN;
        float4 v = reinterpret_cast<const float4*>(row)[j];
        split_store4(v, g_w1h + i * 4, g_w1l + i * 4);
    } else if (bid < 3520) {
        int i = (bid - 3040) * 256 + tid;
        int n = i / (KPAD / 4);
        int c4 = (i % (KPAD / 4)) * 4;
        float4 v = (c4 < DTR) ? *reinterpret_cast<const float4*>(wdt + (size_t)n * DTR + c4)
                              : make_float4(0.f, 0.f, 0.f, 0.f);
        split_store4(v, g_w2h + (size_t)n * KPAD + c4, g_w2l + (size_t)n * KPAD + c4);
    } else {
        int i = (bid - 3520) * 256 + tid;
        float4 v = reinterpret_cast<const float4*>(alog)[i];
        float4 o = make_float4(-__expf(v.x), -__expf(v.y), -__expf(v.z), -__expf(v.w));
        reinterpret_cast<float4*>(g_A2)[i] = o;
    }
}

// ---------------- wmma GEMM, 64m x 64n CTA, 8 warps (4x2), warp = 16m x 32n ----------------
// 3-term hi/lo split, cp.async 2-stage pipeline.
// stage: sAh 5120 | sAl 5120 | sBh 5120 | sBl 5120 = 20480; x2 = 40960
#define STAGE_SZ 20480
#define SMEM_DYN (2 * STAGE_SZ)

template<int MODE>
__global__ __launch_bounds__(256, 3) void gemm_wmma(const float* __restrict__ bias) {
    extern __shared__ __align__(16) char smbuf[];
    const int tid = threadIdx.x;
    const int wid = tid >> 5;
    const int wm = wid >> 1;          // 0..3 -> 16m each
    const int wn = wid & 1;           // 0..1 -> 32n each
    const int mBase = blockIdx.x * 64;
    const int nBase = blockIdx.y * 64;
    const int kOff  = (MODE == 0) ? blockIdx.z * KSPLIT : 0;
    const int nch   = ((MODE == 0) ? KSPLIT : KPAD) / KC;
    const int lda   = (MODE == 0) ? DIN : KPAD;
    const int ldb   = (MODE == 0) ? DIN : KPAD;
    const __nv_bfloat16* aH = (MODE == 0) ? g_xh : g_ph;
    const __nv_bfloat16* aL = (MODE == 0) ? g_xl : g_pl;
    const __nv_bfloat16* bH = (MODE == 0) ? g_w1h : g_w2h;
    const __nv_bfloat16* bL = (MODE == 0) ? g_w1l : g_w2l;

    const int lrow = tid >> 2;         // 0..63
    const int lc16 = tid & 3;          // 16B unit

    auto prefetch = [&](int stage, int k0) {
        char* base = smbuf + stage * STAGE_SZ;
        __nv_bfloat16* sAh = reinterpret_cast<__nv_bfloat16*>(base);
        __nv_bfloat16* sAl = reinterpret_cast<__nv_bfloat16*>(base + 5120);
        __nv_bfloat16* sBh = reinterpret_cast<__nv_bfloat16*>(base + 10240);
        __nv_bfloat16* sBl = reinterpret_cast<__nv_bfloat16*>(base + 15360);
        const size_t goa = (size_t)(mBase + lrow) * lda + k0 + lc16 * 8;
        const size_t gob = (size_t)(nBase + lrow) * ldb + k0 + lc16 * 8;
        cp16(sAh + lrow * PADK + lc16 * 8, aH + goa);
        cp16(sAl + lrow * PADK + lc16 * 8, aL + goa);
        cp16(sBh + lrow * PADK + lc16 * 8, bH + gob);
        cp16(sBl + lrow * PADK + lc16 * 8, bL + gob);
        CP_COMMIT();
    };

    wmma::fragment<wmma::accumulator, 16, 16, 16, float> acc[2];
    wmma::fill_fragment(acc[0], 0.0f);
    wmma::fill_fragment(acc[1], 0.0f);

    prefetch(0, kOff);

    for (int ch = 0; ch < nch; ch++) {
        const int stage = ch & 1;
        if (ch + 1 < nch) {
            prefetch(stage ^ 1, kOff + (ch + 1) * KC);
            CP_WAIT(1);
        } else {
            CP_WAIT(0);
        }
        __syncthreads();

        char* base = smbuf + stage * STAGE_SZ;
        __nv_bfloat16* sAh = reinterpret_cast<__nv_bfloat16*>(base);
        __nv_bfloat16* sAl = reinterpret_cast<__nv_bfloat16*>(base + 5120);
        __nv_bfloat16* sBh = reinterpret_cast<__nv_bfloat16*>(base + 10240);
        __nv_bfloat16* sBl = reinterpret_cast<__nv_bfloat16*>(base + 15360);

#pragma unroll
        for (int kk = 0; kk < 2; kk++) {
            wmma::fragment<wmma::matrix_a, 16, 16, 16, __nv_bfloat16, wmma::row_major> ah, al;
            wmma::fragment<wmma::matrix_b, 16, 16, 16, __nv_bfloat16, wmma::col_major> bh[2], bl[2];
            wmma::load_matrix_sync(ah, sAh + (wm * 16) * PADK + kk * 16, PADK);
            wmma::load_matrix_sync(al, sAl + (wm * 16) * PADK + kk * 16, PADK);
#pragma unroll
            for (int j = 0; j < 2; j++) {
                wmma::load_matrix_sync(bh[j], sBh + (wn * 32 + j * 16) * PADK + kk * 16, PADK);
                wmma::load_matrix_sync(bl[j], sBl + (wn * 32 + j * 16) * PADK + kk * 16, PADK);
            }
#pragma unroll
            for (int j = 0; j < 2; j++) {
                wmma::mma_sync(acc[j], ah, bh[j], acc[j]);
                wmma::mma_sync(acc[j], ah, bl[j], acc[j]);
                wmma::mma_sync(acc[j], al, bh[j], acc[j]);
            }
        }
        __syncthreads();
    }

    if (MODE == 0) {
        float* base = g_partial + ((size_t)blockIdx.z * B_SZ + mBase) * NPROJ + nBase;
#pragma unroll
        for (int j = 0; j < 2; j++) {
            float* p = base + (size_t)(wm * 16) * NPROJ + wn * 32 + j * 16;
            wmma::store_matrix_sync(p, acc[j], NPROJ, wmma::mem_row_major);
        }
    } else {
        float* stage = reinterpret_cast<float*>(smbuf);   // 64 x 68 f32 = 17408B < SMEM_DYN
#pragma unroll
        for (int j = 0; j < 2; j++) {
            float* p = stage + (size_t)(wm * 16) * 68 + wn * 32 + j * 16;
            wmma::store_matrix_sync(p, acc[j], 68, wmma::mem_row_major);
        }
        __syncthreads();
        // 64 rows x 16 float4 = 1024; 4 per thread
#pragma unroll
        for (int s = 0; s < 4; s++) {
            int u = tid + s * 256;
            int row = u >> 4, c4 = (u & 15) * 4;
            float4 v = *reinterpret_cast<float4*>(stage + row * 68 + c4);
            const int gn = nBase + c4;
            v.x += __ldg(bias + gn);     v.y += __ldg(bias + gn + 1);
            v.z += __ldg(bias + gn + 2); v.w += __ldg(bias + gn + 3);
            float4 o;
            o.x = fmaxf(v.x, 0.f) + log1pf(__expf(-fabsf(v.x)));
            o.y = fmaxf(v.y, 0.f) + log1pf(__expf(-fabsf(v.y)));
            o.z = fmaxf(v.z, 0.f) + log1pf(__expf(-fabsf(v.z)));
            o.w = fmaxf(v.w, 0.f) + log1pf(__expf(-fabsf(v.w)));
            *reinterpret_cast<float4*>(g_dt + (size_t)(mBase + row) * DIN + gn) = o;
        }
    }
}

// ---------------- split-K reduce + bf16 split of proj ----------------
__global__ void reduce_kernel() {
    int i = blockIdx.x * blockDim.x + threadIdx.x;
    const int total = B_SZ * NPROJ;
    if (i >= total) return;
    float s = g_partial[i];
#pragma unroll
    for (int z = 1; z < SPLITK; z++) s += g_partial[(size_t)z * total + i];
    g_proj[i] = s;
    __nv_bfloat16 hi, lo;
    split2(s, hi, lo);
    g_ph[i] = hi; g_pl[i] = lo;
}

// ---------------- elementwise SSM ----------------
__global__ __launch_bounds__(256) void ssm_kernel(const float* __restrict__ x,
                                                  const float* __restrict__ h,
                                                  const float* __restrict__ Dv,
                                                  float* __restrict__ y) {
    __shared__ float ys[64];
    const int b = blockIdx.y;
    const int dBase = blockIdx.x * 64;
    const int tid = threadIdx.x;
    const int l4 = tid & 3;
    const int d = dBase + (tid >> 2);
    const int pair = b * DIN + d;

    const float dt_v = g_dt[pair];
    const float x_v = x[pair];
    const float4 h4  = *reinterpret_cast<const float4*>(h + (size_t)pair * DST + l4 * 4);
    const float4 A4  = *reinterpret_cast<const float4*>(g_A2 + (size_t)d * DST + l4 * 4);
    const float4 Bt4 = *reinterpret_cast<const float4*>(g_proj + (size_t)b * NPROJ + DTR + l4 * 4);
    const float4 Ct4 = *reinterpret_cast<const float4*>(g_proj + (size_t)b * NPROJ + DTR + DST + l4 * 4);

    const float dx = dt_v * x_v;
    float acc;
    {
        float e0 = __expf(dt_v * A4.x);
        float e1 = __expf(dt_v * A4.y);
        float e2 = __expf(dt_v * A4.z);
        float e3 = __expf(dt_v * A4.w);
        float hn0 = fmaf(e0, h4.x, dx * Bt4.x);
        float hn1 = fmaf(e1, h4.y, dx * Bt4.y);
        float hn2 = fmaf(e2, h4.z, dx * Bt4.z);
        float hn3 = fmaf(e3, h4.w, dx * Bt4.w);
        acc = hn0 * Ct4.x;
        acc = fmaf(hn1, Ct4.y, acc);
        acc = fmaf(hn2, Ct4.z, acc);
        acc = fmaf(hn3, Ct4.w, acc);
    }
    acc += __shfl_xor_sync(0xffffffffu, acc, 1);
    acc += __shfl_xor_sync(0xffffffffu, acc, 2);
    if (l4 == 0) ys[tid >> 2] = fmaf(Dv[d], x_v, acc);
    __syncthreads();
    if (tid < 64) y[(size_t)b * DIN + dBase + tid] = ys[tid];
}

// ---------------- launch ----------------
extern "C" void kernel_launch(void* const* d_in, const int* in_sizes, int n_in,
                              void* d_out, int out_size) {
    const float* x      = (const float*)d_in[0];
    const float* h      = (const float*)d_in[1];
    const float* wdtlow = (const float*)d_in[2];
    const float* wdt    = (const float*)d_in[3];
    const float* bdt    = (const float*)d_in[4];
    const float* wb     = (const float*)d_in[5];
    const float* wc     = (const float*)d_in[6];
    const float* alog   = (const float*)d_in[7];
    const float* Dv     = (const float*)d_in[8];
    float* y = (float*)d_out;

    cudaFuncSetAttribute(gemm_wmma<0>, cudaFuncAttributeMaxDynamicSharedMemorySize, SMEM_DYN);
    cudaFuncSetAttribute(gemm_wmma<1>, cudaFuncAttributeMaxDynamicSharedMemorySize, SMEM_DYN);

    prep_all<<<PREP_BLOCKS, 256>>>(x, wdtlow, wb, wc, wdt, alog);
    gemm_wmma<0><<<dim3(B_SZ / 64, NPROJ / 64, SPLITK), 256, SMEM_DYN>>>(bdt);
    reduce_kernel<<<(B_SZ * NPROJ + 255) / 256, 256>>>();
    gemm_wmma<1><<<dim3(B_SZ / 64, DIN / 64, 1), 256, SMEM_DYN>>>(bdt);
    ssm_kernel<<<dim3(DIN / 64, B_SZ), 256>>>(x, h, Dv, y);
}

// round 10
// speedup vs baseline: 1.0372x; 1.0372x over previous
#include <cuda_runtime.h>
#include <cuda_bf16.h>
#include <mma.h>
#include <math.h>
#include <stdint.h>

using namespace nvcuda;

// 0: x [1024,2560]  1: h [1024,2560,16]  2: W_dt_low [160,2560]  3: W_dt [2560,160]
// 4: b_dt [2560]    5: W_B [16,2560]     6: W_C [16,2560]        7: A_log [2560,16]
// 8: D [2560]       out: y [1024,2560]   all f32

#define B_SZ    1024
#define DIN     2560
#define DST     16
#define DTR     160
#define NPROJ   192
#define KPAD    192
#define SPLITK  8
#define KSPLIT  (DIN / SPLITK)   // 320
#define KC      64               // k per smem chunk (4 kk-steps)
#define PADK    72               // padded k-stride (144B rows; LDSM conflict-free)

// ---------------- device scratch ----------------
__device__ __align__(16) __nv_bfloat16 g_xh[B_SZ * DIN], g_xl[B_SZ * DIN];
__device__ __align__(16) __nv_bfloat16 g_w1h[NPROJ * DIN], g_w1l[NPROJ * DIN];
__device__ __align__(16) __nv_bfloat16 g_w2h[DIN * KPAD], g_w2l[DIN * KPAD];
__device__ __align__(16) __nv_bfloat16 g_ph[B_SZ * KPAD], g_pl[B_SZ * KPAD];
__device__ __align__(16) float g_partial[SPLITK * B_SZ * NPROJ];
__device__ __align__(16) float g_proj[B_SZ * NPROJ];
__device__ __align__(16) float g_dt[B_SZ * DIN];
__device__ __align__(16) float g_A2[DIN * DST];

// ---------------- helpers ----------------
__device__ __forceinline__ void split2(float v, __nv_bfloat16& hi, __nv_bfloat16& lo) {
    hi = __float2bfloat16(v);
    lo = __float2bfloat16(v - __bfloat162float(hi));
}
__device__ __forceinline__ void split_store4(float4 v, __nv_bfloat16* ph, __nv_bfloat16* pl) {
    __nv_bfloat16 h0, h1, h2, h3, l0, l1, l2, l3;
    split2(v.x, h0, l0); split2(v.y, h1, l1); split2(v.z, h2, l2); split2(v.w, h3, l3);
    reinterpret_cast<__nv_bfloat162*>(ph)[0] = __nv_bfloat162(h0, h1);
    reinterpret_cast<__nv_bfloat162*>(ph)[1] = __nv_bfloat162(h2, h3);
    reinterpret_cast<__nv_bfloat162*>(pl)[0] = __nv_bfloat162(l0, l1);
    reinterpret_cast<__nv_bfloat162*>(pl)[1] = __nv_bfloat162(l2, l3);
}
__device__ __forceinline__ void cp16(void* sdst, const void* gsrc) {
    asm volatile("cp.async.cg.shared.global [%0], [%1], 16;"
        :: "r"((uint32_t)__cvta_generic_to_shared(sdst)), "l"(gsrc));
}
#define CP_COMMIT() asm volatile("cp.async.commit_group;" ::: "memory")
#define CP_WAIT(N)  asm volatile("cp.async.wait_group %0;" :: "n"(N) : "memory")

// ---------------- fused prep ----------------
#define PREP_BLOCKS 3560
__global__ __launch_bounds__(256) void prep_all(const float* __restrict__ x,
                                                const float* __restrict__ wdtlow,
                                                const float* __restrict__ wb,
                                                const float* __restrict__ wc,
                                                const float* __restrict__ wdt,
                                                const float* __restrict__ alog) {
    const int bid = blockIdx.x;
    const int tid = threadIdx.x;
    if (bid < 2560) {
        int i = bid * 256 + tid;
        float4 v = reinterpret_cast<const float4*>(x)[i];
        split_store4(v, g_xh + i * 4, g_xl + i * 4);
    } else if (bid < 3040) {
        int i = (bid - 2560) * 256 + tid;
        int n = i / (DIN / 4);
        int j = i % (DIN / 4);
        const float* row = (n < DTR) ? wdtlow + (size_t)n * DIN
                         : (n < DTR + DST) ? wb + (size_t)(n - DTR) * DIN
                         : wc + (size_t)(n - DTR - DST) * DIN;
        float4 v = reinterpret_cast<const float4*>(row)[j];
        split_store4(v, g_w1h + i * 4, g_w1l + i * 4);
    } else if (bid < 3520) {
        int i = (bid - 3040) * 256 + tid;
        int n = i / (KPAD / 4);
        int c4 = (i % (KPAD / 4)) * 4;
        float4 v = (c4 < DTR) ? *reinterpret_cast<const float4*>(wdt + (size_t)n * DTR + c4)
                              : make_float4(0.f, 0.f, 0.f, 0.f);
        split_store4(v, g_w2h + (size_t)n * KPAD + c4, g_w2l + (size_t)n * KPAD + c4);
    } else {
        int i = (bid - 3520) * 256 + tid;
        float4 v = reinterpret_cast<const float4*>(alog)[i];
        float4 o = make_float4(-__expf(v.x), -__expf(v.y), -__expf(v.z), -__expf(v.w));
        reinterpret_cast<float4*>(g_A2)[i] = o;
    }
}

// ---------------- wmma GEMM, 64m x 64n CTA, 8 warps (4x2), warp = 16m x 32n ----------------
// 3-term hi/lo split into 3 INDEPENDENT accumulator banks; KC=64; cp.async 2-stage.
// stage: sAh 9216 | sAl 9216 | sBh 9216 | sBl 9216 = 36864; x2 = 73728
#define STAGE_SZ 36864
#define SMEM_DYN (2 * STAGE_SZ)

template<int MODE>
__global__ __launch_bounds__(256, 2) void gemm_wmma(const float* __restrict__ bias) {
    extern __shared__ __align__(16) char smbuf[];
    const int tid = threadIdx.x;
    const int wid = tid >> 5;
    const int wm = wid >> 1;          // 0..3 -> 16m each
    const int wn = wid & 1;           // 0..1 -> 32n each
    const int mBase = blockIdx.x * 64;
    const int nBase = blockIdx.y * 64;
    const int kOff  = (MODE == 0) ? blockIdx.z * KSPLIT : 0;
    const int nch   = ((MODE == 0) ? KSPLIT : KPAD) / KC;   // 5 or 3
    const int lda   = (MODE == 0) ? DIN : KPAD;
    const int ldb   = (MODE == 0) ? DIN : KPAD;
    const __nv_bfloat16* aH = (MODE == 0) ? g_xh : g_ph;
    const __nv_bfloat16* aL = (MODE == 0) ? g_xl : g_pl;
    const __nv_bfloat16* bH = (MODE == 0) ? g_w1h : g_w2h;
    const __nv_bfloat16* bL = (MODE == 0) ? g_w1l : g_w2l;

    auto prefetch = [&](int stage, int k0) {
        char* base = smbuf + stage * STAGE_SZ;
        __nv_bfloat16* sAh = reinterpret_cast<__nv_bfloat16*>(base);
        __nv_bfloat16* sAl = reinterpret_cast<__nv_bfloat16*>(base + 9216);
        __nv_bfloat16* sBh = reinterpret_cast<__nv_bfloat16*>(base + 18432);
        __nv_bfloat16* sBl = reinterpret_cast<__nv_bfloat16*>(base + 27648);
        // 64 rows x 8 c16 = 512 slots per matrix; 2 per thread per matrix
#pragma unroll
        for (int s = 0; s < 2; s++) {
            int u = tid + s * 256;
            int row = u >> 3, c16 = u & 7;
            const size_t goa = (size_t)(mBase + row) * lda + k0 + c16 * 8;
            const size_t gob = (size_t)(nBase + row) * ldb + k0 + c16 * 8;
            cp16(sAh + row * PADK + c16 * 8, aH + goa);
            cp16(sAl + row * PADK + c16 * 8, aL + goa);
            cp16(sBh + row * PADK + c16 * 8, bH + gob);
            cp16(sBl + row * PADK + c16 * 8, bL + gob);
        }
        CP_COMMIT();
    };

    // 3 independent accumulator banks: [term][j]
    wmma::fragment<wmma::accumulator, 16, 16, 16, float> accT[3][2];
#pragma unroll
    for (int t = 0; t < 3; t++) {
        wmma::fill_fragment(accT[t][0], 0.0f);
        wmma::fill_fragment(accT[t][1], 0.0f);
    }

    prefetch(0, kOff);

    for (int ch = 0; ch < nch; ch++) {
        const int stage = ch & 1;
        if (ch + 1 < nch) {
            prefetch(stage ^ 1, kOff + (ch + 1) * KC);
            CP_WAIT(1);
        } else {
            CP_WAIT(0);
        }
        __syncthreads();

        char* base = smbuf + stage * STAGE_SZ;
        __nv_bfloat16* sAh = reinterpret_cast<__nv_bfloat16*>(base);
        __nv_bfloat16* sAl = reinterpret_cast<__nv_bfloat16*>(base + 9216);
        __nv_bfloat16* sBh = reinterpret_cast<__nv_bfloat16*>(base + 18432);
        __nv_bfloat16* sBl = reinterpret_cast<__nv_bfloat16*>(base + 27648);

#pragma unroll
        for (int kk = 0; kk < 4; kk++) {
            wmma::fragment<wmma::matrix_a, 16, 16, 16, __nv_bfloat16, wmma::row_major> ah, al;
            wmma::fragment<wmma::matrix_b, 16, 16, 16, __nv_bfloat16, wmma::col_major> bh[2], bl[2];
            wmma::load_matrix_sync(ah, sAh + (wm * 16) * PADK + kk * 16, PADK);
            wmma::load_matrix_sync(al, sAl + (wm * 16) * PADK + kk * 16, PADK);
#pragma unroll
            for (int j = 0; j < 2; j++) {
                wmma::load_matrix_sync(bh[j], sBh + (wn * 32 + j * 16) * PADK + kk * 16, PADK);
                wmma::load_matrix_sync(bl[j], sBl + (wn * 32 + j * 16) * PADK + kk * 16, PADK);
            }
            // all 6 mma are independent (distinct accumulators)
#pragma unroll
            for (int j = 0; j < 2; j++) {
                wmma::mma_sync(accT[0][j], ah, bh[j], accT[0][j]);
                wmma::mma_sync(accT[1][j], ah, bl[j], accT[1][j]);
                wmma::mma_sync(accT[2][j], al, bh[j], accT[2][j]);
            }
        }
        __syncthreads();
    }

    // fold term banks
    wmma::fragment<wmma::accumulator, 16, 16, 16, float> acc[2];
#pragma unroll
    for (int j = 0; j < 2; j++) {
#pragma unroll
        for (int e = 0; e < acc[j].num_elements; e++)
            acc[j].x[e] = accT[0][j].x[e] + accT[1][j].x[e] + accT[2][j].x[e];
    }

    if (MODE == 0) {
        float* base = g_partial + ((size_t)blockIdx.z * B_SZ + mBase) * NPROJ + nBase;
#pragma unroll
        for (int j = 0; j < 2; j++) {
            float* p = base + (size_t)(wm * 16) * NPROJ + wn * 32 + j * 16;
            wmma::store_matrix_sync(p, acc[j], NPROJ, wmma::mem_row_major);
        }
    } else {
        float* stage = reinterpret_cast<float*>(smbuf);   // 64 x 68 f32 = 17408B < SMEM_DYN
#pragma unroll
        for (int j = 0; j < 2; j++) {
            float* p = stage + (size_t)(wm * 16) * 68 + wn * 32 + j * 16;
            wmma::store_matrix_sync(p, acc[j], 68, wmma::mem_row_major);
        }
        __syncthreads();
#pragma unroll
        for (int s = 0; s < 4; s++) {
            int u = tid + s * 256;
            int row = u >> 4, c4 = (u & 15) * 4;
            float4 v = *reinterpret_cast<float4*>(stage + row * 68 + c4);
            const int gn = nBase + c4;
            v.x += __ldg(bias + gn);     v.y += __ldg(bias + gn + 1);
            v.z += __ldg(bias + gn + 2); v.w += __ldg(bias + gn + 3);
            float4 o;
            o.x = fmaxf(v.x, 0.f) + log1pf(__expf(-fabsf(v.x)));
            o.y = fmaxf(v.y, 0.f) + log1pf(__expf(-fabsf(v.y)));
            o.z = fmaxf(v.z, 0.f) + log1pf(__expf(-fabsf(v.z)));
            o.w = fmaxf(v.w, 0.f) + log1pf(__expf(-fabsf(v.w)));
            *reinterpret_cast<float4*>(g_dt + (size_t)(mBase + row) * DIN + gn) = o;
        }
    }
}

// ---------------- split-K reduce + bf16 split of proj ----------------
__global__ void reduce_kernel() {
    int i = blockIdx.x * blockDim.x + threadIdx.x;
    const int total = B_SZ * NPROJ;
    if (i >= total) return;
    float s = g_partial[i];
#pragma unroll
    for (int z = 1; z < SPLITK; z++) s += g_partial[(size_t)z * total + i];
    g_proj[i] = s;
    __nv_bfloat16 hi, lo;
    split2(s, hi, lo);
    g_ph[i] = hi; g_pl[i] = lo;
}

// ---------------- elementwise SSM ----------------
__global__ __launch_bounds__(256) void ssm_kernel(const float* __restrict__ x,
                                                  const float* __restrict__ h,
                                                  const float* __restrict__ Dv,
                                                  float* __restrict__ y) {
    __shared__ float ys[64];
    const int b = blockIdx.y;
    const int dBase = blockIdx.x * 64;
    const int tid = threadIdx.x;
    const int l4 = tid & 3;
    const int d = dBase + (tid >> 2);
    const int pair = b * DIN + d;

    const float dt_v = g_dt[pair];
    const float x_v = x[pair];
    const float4 h4  = *reinterpret_cast<const float4*>(h + (size_t)pair * DST + l4 * 4);
    const float4 A4  = *reinterpret_cast<const float4*>(g_A2 + (size_t)d * DST + l4 * 4);
    const float4 Bt4 = *reinterpret_cast<const float4*>(g_proj + (size_t)b * NPROJ + DTR + l4 * 4);
    const float4 Ct4 = *reinterpret_cast<const float4*>(g_proj + (size_t)b * NPROJ + DTR + DST + l4 * 4);

    const float dx = dt_v * x_v;
    float acc;
    {
        float e0 = __expf(dt_v * A4.x);
        float e1 = __expf(dt_v * A4.y);
        float e2 = __expf(dt_v * A4.z);
        float e3 = __expf(dt_v * A4.w);
        float hn0 = fmaf(e0, h4.x, dx * Bt4.x);
        float hn1 = fmaf(e1, h4.y, dx * Bt4.y);
        float hn2 = fmaf(e2, h4.z, dx * Bt4.z);
        float hn3 = fmaf(e3, h4.w, dx * Bt4.w);
        acc = hn0 * Ct4.x;
        acc = fmaf(hn1, Ct4.y, acc);
        acc = fmaf(hn2, Ct4.z, acc);
        acc = fmaf(hn3, Ct4.w, acc);
    }
    acc += __shfl_xor_sync(0xffffffffu, acc, 1);
    acc += __shfl_xor_sync(0xffffffffu, acc, 2);
    if (l4 == 0) ys[tid >> 2] = fmaf(Dv[d], x_v, acc);
    __syncthreads();
    if (tid < 64) y[(size_t)b * DIN + dBase + tid] = ys[tid];
}

// ---------------- launch ----------------
extern "C" void kernel_launch(void* const* d_in, const int* in_sizes, int n_in,
                              void* d_out, int out_size) {
    const float* x      = (const float*)d_in[0];
    const float* h      = (const float*)d_in[1];
    const float* wdtlow = (const float*)d_in[2];
    const float* wdt    = (const float*)d_in[3];
    const float* bdt    = (const float*)d_in[4];
    const float* wb     = (const float*)d_in[5];
    const float* wc     = (const float*)d_in[6];
    const float* alog   = (const float*)d_in[7];
    const float* Dv     = (const float*)d_in[8];
    float* y = (float*)d_out;

    cudaFuncSetAttribute(gemm_wmma<0>, cudaFuncAttributeMaxDynamicSharedMemorySize, SMEM_DYN);
    cudaFuncSetAttribute(gemm_wmma<1>, cudaFuncAttributeMaxDynamicSharedMemorySize, SMEM_DYN);

    prep_all<<<PREP_BLOCKS, 256>>>(x, wdtlow, wb, wc, wdt, alog);
    gemm_wmma<0><<<dim3(B_SZ / 64, NPROJ / 64, SPLITK), 256, SMEM_DYN>>>(bdt);
    reduce_kernel<<<(B_SZ * NPROJ + 255) / 256, 256>>>();
    gemm_wmma<1><<<dim3(B_SZ / 64, DIN / 64, 1), 256, SMEM_DYN>>>(bdt);
    ssm_kernel<<<dim3(DIN / 64, B_SZ), 256>>>(x, h, Dv, y);
}

// round 11
// speedup vs baseline: 1.0401x; 1.0028x over previous
#include <cuda_runtime.h>
#include <cuda_bf16.h>
#include <mma.h>
#include <math.h>
#include <stdint.h>

using namespace nvcuda;

// 0: x [1024,2560]  1: h [1024,2560,16]  2: W_dt_low [160,2560]  3: W_dt [2560,160]
// 4: b_dt [2560]    5: W_B [16,2560]     6: W_C [16,2560]        7: A_log [2560,16]
// 8: D [2560]       out: y [1024,2560]   all f32

#define B_SZ    1024
#define DIN     2560
#define DST     16
#define DTR     160
#define NPROJ   192
#define KPAD    192
#define SPLITK  8
#define KSPLIT  (DIN / SPLITK)   // 320
#define KC      64               // 4 kk-steps per chunk
#define PADK    72

// ---------------- device scratch ----------------
__device__ __align__(16) __nv_bfloat16 g_xh[B_SZ * DIN], g_xl[B_SZ * DIN];
__device__ __align__(16) __nv_bfloat16 g_w1h[NPROJ * DIN], g_w1l[NPROJ * DIN];
__device__ __align__(16) __nv_bfloat16 g_w2h[DIN * KPAD], g_w2l[DIN * KPAD];
__device__ __align__(16) __nv_bfloat16 g_ph[B_SZ * KPAD], g_pl[B_SZ * KPAD];
__device__ __align__(16) float g_partial[SPLITK * B_SZ * NPROJ];
__device__ __align__(16) float g_proj[B_SZ * NPROJ];
__device__ __align__(16) float g_dt[B_SZ * DIN];
__device__ __align__(16) float g_A2[DIN * DST];

// ---------------- helpers ----------------
__device__ __forceinline__ void split2(float v, __nv_bfloat16& hi, __nv_bfloat16& lo) {
    hi = __float2bfloat16(v);
    lo = __float2bfloat16(v - __bfloat162float(hi));
}
__device__ __forceinline__ void split_store4(float4 v, __nv_bfloat16* ph, __nv_bfloat16* pl) {
    __nv_bfloat16 h0, h1, h2, h3, l0, l1, l2, l3;
    split2(v.x, h0, l0); split2(v.y, h1, l1); split2(v.z, h2, l2); split2(v.w, h3, l3);
    reinterpret_cast<__nv_bfloat162*>(ph)[0] = __nv_bfloat162(h0, h1);
    reinterpret_cast<__nv_bfloat162*>(ph)[1] = __nv_bfloat162(h2, h3);
    reinterpret_cast<__nv_bfloat162*>(pl)[0] = __nv_bfloat162(l0, l1);
    reinterpret_cast<__nv_bfloat162*>(pl)[1] = __nv_bfloat162(l2, l3);
}
__device__ __forceinline__ void cp16(void* sdst, const void* gsrc) {
    asm volatile("cp.async.cg.shared.global [%0], [%1], 16;"
        :: "r"((uint32_t)__cvta_generic_to_shared(sdst)), "l"(gsrc));
}
#define CP_COMMIT() asm volatile("cp.async.commit_group;" ::: "memory")
#define CP_WAIT(N)  asm volatile("cp.async.wait_group %0;" :: "n"(N) : "memory")

// ---------------- fused prep ----------------
#define PREP_BLOCKS 3560
__global__ __launch_bounds__(256) void prep_all(const float* __restrict__ x,
                                                const float* __restrict__ wdtlow,
                                                const float* __restrict__ wb,
                                                const float* __restrict__ wc,
                                                const float* __restrict__ wdt,
                                                const float* __restrict__ alog) {
    const int bid = blockIdx.x;
    const int tid = threadIdx.x;
    if (bid < 2560) {
        int i = bid * 256 + tid;
        float4 v = reinterpret_cast<const float4*>(x)[i];
        split_store4(v, g_xh + i * 4, g_xl + i * 4);
    } else if (bid < 3040) {
        int i = (bid - 2560) * 256 + tid;
        int n = i / (DIN / 4);
        int j = i % (DIN / 4);
        const float* row = (n < DTR) ? wdtlow + (size_t)n * DIN
                         : (n < DTR + DST) ? wb + (size_t)(n - DTR) * DIN
                         : wc + (size_t)(n - DTR - DST) * DIN;
        float4 v = reinterpret_cast<const float4*>(row)[j];
        split_store4(v, g_w1h + i * 4, g_w1l + i * 4);
    } else if (bid < 3520) {
        int i = (bid - 3040) * 256 + tid;
        int n = i / (KPAD / 4);
        int c4 = (i % (KPAD / 4)) * 4;
        float4 v = (c4 < DTR) ? *reinterpret_cast<const float4*>(wdt + (size_t)n * DTR + c4)
                              : make_float4(0.f, 0.f, 0.f, 0.f);
        split_store4(v, g_w2h + (size_t)n * KPAD + c4, g_w2l + (size_t)n * KPAD + c4);
    } else {
        int i = (bid - 3520) * 256 + tid;
        float4 v = reinterpret_cast<const float4*>(alog)[i];
        float4 o = make_float4(-__expf(v.x), -__expf(v.y), -__expf(v.z), -__expf(v.w));
        reinterpret_cast<float4*>(g_A2)[i] = o;
    }
}

// ---------------- wmma GEMM, 64m x 64n CTA, 8 warps (4x2), warp = 16m x 32n ----------------
// 2 acc banks (bank0 = ah*bh; bank1 = ah*bl + al*bh); register double-buffered fragments.
// stage: sAh 9216 | sAl 9216 | sBh 9216 | sBl 9216 = 36864; x2 = 73728
#define STAGE_SZ 36864
#define SMEM_DYN (2 * STAGE_SZ)

typedef wmma::fragment<wmma::matrix_a, 16, 16, 16, __nv_bfloat16, wmma::row_major> FragA;
typedef wmma::fragment<wmma::matrix_b, 16, 16, 16, __nv_bfloat16, wmma::col_major> FragB;
typedef wmma::fragment<wmma::accumulator, 16, 16, 16, float> FragC;

template<int MODE>
__global__ __launch_bounds__(256, 2) void gemm_wmma(const float* __restrict__ bias) {
    extern __shared__ __align__(16) char smbuf[];
    const int tid = threadIdx.x;
    const int wid = tid >> 5;
    const int wm = wid >> 1;
    const int wn = wid & 1;
    const int mBase = blockIdx.x * 64;
    const int nBase = blockIdx.y * 64;
    const int kOff  = (MODE == 0) ? blockIdx.z * KSPLIT : 0;
    const int nch   = ((MODE == 0) ? KSPLIT : KPAD) / KC;
    const int lda   = (MODE == 0) ? DIN : KPAD;
    const int ldb   = (MODE == 0) ? DIN : KPAD;
    const __nv_bfloat16* aH = (MODE == 0) ? g_xh : g_ph;
    const __nv_bfloat16* aL = (MODE == 0) ? g_xl : g_pl;
    const __nv_bfloat16* bH = (MODE == 0) ? g_w1h : g_w2h;
    const __nv_bfloat16* bL = (MODE == 0) ? g_w1l : g_w2l;

    auto prefetch = [&](int stage, int k0) {
        char* base = smbuf + stage * STAGE_SZ;
        __nv_bfloat16* sAh = reinterpret_cast<__nv_bfloat16*>(base);
        __nv_bfloat16* sAl = reinterpret_cast<__nv_bfloat16*>(base + 9216);
        __nv_bfloat16* sBh = reinterpret_cast<__nv_bfloat16*>(base + 18432);
        __nv_bfloat16* sBl = reinterpret_cast<__nv_bfloat16*>(base + 27648);
#pragma unroll
        for (int s = 0; s < 2; s++) {
            int u = tid + s * 256;
            int row = u >> 3, c16 = u & 7;
            const size_t goa = (size_t)(mBase + row) * lda + k0 + c16 * 8;
            const size_t gob = (size_t)(nBase + row) * ldb + k0 + c16 * 8;
            cp16(sAh + row * PADK + c16 * 8, aH + goa);
            cp16(sAl + row * PADK + c16 * 8, aL + goa);
            cp16(sBh + row * PADK + c16 * 8, bH + gob);
            cp16(sBl + row * PADK + c16 * 8, bL + gob);
        }
        CP_COMMIT();
    };

    FragC acc0[2], acc1[2];
#pragma unroll
    for (int j = 0; j < 2; j++) { wmma::fill_fragment(acc0[j], 0.0f); wmma::fill_fragment(acc1[j], 0.0f); }

    prefetch(0, kOff);

    // register-double-buffered fragments
    FragA ah[2], al[2];
    FragB bh[2][2], bl[2][2];

    for (int ch = 0; ch < nch; ch++) {
        const int stage = ch & 1;
        if (ch + 1 < nch) {
            prefetch(stage ^ 1, kOff + (ch + 1) * KC);
            CP_WAIT(1);
        } else {
            CP_WAIT(0);
        }
        __syncthreads();

        char* base = smbuf + stage * STAGE_SZ;
        __nv_bfloat16* sAh = reinterpret_cast<__nv_bfloat16*>(base);
        __nv_bfloat16* sAl = reinterpret_cast<__nv_bfloat16*>(base + 9216);
        __nv_bfloat16* sBh = reinterpret_cast<__nv_bfloat16*>(base + 18432);
        __nv_bfloat16* sBl = reinterpret_cast<__nv_bfloat16*>(base + 27648);

        // load kk=0 fragments into buffer 0
        wmma::load_matrix_sync(ah[0], sAh + (wm * 16) * PADK, PADK);
        wmma::load_matrix_sync(al[0], sAl + (wm * 16) * PADK, PADK);
#pragma unroll
        for (int j = 0; j < 2; j++) {
            wmma::load_matrix_sync(bh[0][j], sBh + (wn * 32 + j * 16) * PADK, PADK);
            wmma::load_matrix_sync(bl[0][j], sBl + (wn * 32 + j * 16) * PADK, PADK);
        }

#pragma unroll
        for (int kk = 0; kk < 4; kk++) {
            const int cur = kk & 1, nxt = cur ^ 1;
            if (kk < 3) {
                // prefetch next kk's fragments BEFORE consuming current -> LDSM overlaps HMMA
                wmma::load_matrix_sync(ah[nxt], sAh + (wm * 16) * PADK + (kk + 1) * 16, PADK);
                wmma::load_matrix_sync(al[nxt], sAl + (wm * 16) * PADK + (kk + 1) * 16, PADK);
#pragma unroll
                for (int j = 0; j < 2; j++) {
                    wmma::load_matrix_sync(bh[nxt][j], sBh + (wn * 32 + j * 16) * PADK + (kk + 1) * 16, PADK);
                    wmma::load_matrix_sync(bl[nxt][j], sBl + (wn * 32 + j * 16) * PADK + (kk + 1) * 16, PADK);
                }
            }
            // 6 MMAs on current buffer; acc1 chains are depth-2, interleaved across j
            wmma::mma_sync(acc0[0], ah[cur], bh[cur][0], acc0[0]);
            wmma::mma_sync(acc0[1], ah[cur], bh[cur][1], acc0[1]);
            wmma::mma_sync(acc1[0], ah[cur], bl[cur][0], acc1[0]);
            wmma::mma_sync(acc1[1], ah[cur], bl[cur][1], acc1[1]);
            wmma::mma_sync(acc1[0], al[cur], bh[cur][0], acc1[0]);
            wmma::mma_sync(acc1[1], al[cur], bh[cur][1], acc1[1]);
        }
        __syncthreads();
    }

    // fold banks
    FragC acc[2];
#pragma unroll
    for (int j = 0; j < 2; j++) {
#pragma unroll
        for (int e = 0; e < acc[j].num_elements; e++)
            acc[j].x[e] = acc0[j].x[e] + acc1[j].x[e];
    }

    if (MODE == 0) {
        float* base = g_partial + ((size_t)blockIdx.z * B_SZ + mBase) * NPROJ + nBase;
#pragma unroll
        for (int j = 0; j < 2; j++) {
            float* p = base + (size_t)(wm * 16) * NPROJ + wn * 32 + j * 16;
            wmma::store_matrix_sync(p, acc[j], NPROJ, wmma::mem_row_major);
        }
    } else {
        float* stage = reinterpret_cast<float*>(smbuf);
#pragma unroll
        for (int j = 0; j < 2; j++) {
            float* p = stage + (size_t)(wm * 16) * 68 + wn * 32 + j * 16;
            wmma::store_matrix_sync(p, acc[j], 68, wmma::mem_row_major);
        }
        __syncthreads();
#pragma unroll
        for (int s = 0; s < 4; s++) {
            int u = tid + s * 256;
            int row = u >> 4, c4 = (u & 15) * 4;
            float4 v = *reinterpret_cast<float4*>(stage + row * 68 + c4);
            const int gn = nBase + c4;
            v.x += __ldg(bias + gn);     v.y += __ldg(bias + gn + 1);
            v.z += __ldg(bias + gn + 2); v.w += __ldg(bias + gn + 3);
            float4 o;
            o.x = fmaxf(v.x, 0.f) + log1pf(__expf(-fabsf(v.x)));
            o.y = fmaxf(v.y, 0.f) + log1pf(__expf(-fabsf(v.y)));
            o.z = fmaxf(v.z, 0.f) + log1pf(__expf(-fabsf(v.z)));
            o.w = fmaxf(v.w, 0.f) + log1pf(__expf(-fabsf(v.w)));
            *reinterpret_cast<float4*>(g_dt + (size_t)(mBase + row) * DIN + gn) = o;
        }
    }
}

// ---------------- split-K reduce + bf16 split of proj ----------------
__global__ void reduce_kernel() {
    int i = blockIdx.x * blockDim.x + threadIdx.x;
    const int total = B_SZ * NPROJ;
    if (i >= total) return;
    float s = g_partial[i];
#pragma unroll
    for (int z = 1; z < SPLITK; z++) s += g_partial[(size_t)z * total + i];
    g_proj[i] = s;
    __nv_bfloat16 hi, lo;
    split2(s, hi, lo);
    g_ph[i] = hi; g_pl[i] = lo;
}

// ---------------- elementwise SSM ----------------
__global__ __launch_bounds__(256) void ssm_kernel(const float* __restrict__ x,
                                                  const float* __restrict__ h,
                                                  const float* __restrict__ Dv,
                                                  float* __restrict__ y) {
    __shared__ float ys[64];
    const int b = blockIdx.y;
    const int dBase = blockIdx.x * 64;
    const int tid = threadIdx.x;
    const int l4 = tid & 3;
    const int d = dBase + (tid >> 2);
    const int pair = b * DIN + d;

    const float dt_v = g_dt[pair];
    const float x_v = x[pair];
    const float4 h4  = *reinterpret_cast<const float4*>(h + (size_t)pair * DST + l4 * 4);
    const float4 A4  = *reinterpret_cast<const float4*>(g_A2 + (size_t)d * DST + l4 * 4);
    const float4 Bt4 = *reinterpret_cast<const float4*>(g_proj + (size_t)b * NPROJ + DTR + l4 * 4);
    const float4 Ct4 = *reinterpret_cast<const float4*>(g_proj + (size_t)b * NPROJ + DTR + DST + l4 * 4);

    const float dx = dt_v * x_v;
    float acc;
    {
        float e0 = __expf(dt_v * A4.x);
        float e1 = __expf(dt_v * A4.y);
        float e2 = __expf(dt_v * A4.z);
        float e3 = __expf(dt_v * A4.w);
        float hn0 = fmaf(e0, h4.x, dx * Bt4.x);
        float hn1 = fmaf(e1, h4.y, dx * Bt4.y);
        float hn2 = fmaf(e2, h4.z, dx * Bt4.z);
        float hn3 = fmaf(e3, h4.w, dx * Bt4.w);
        acc = hn0 * Ct4.x;
        acc = fmaf(hn1, Ct4.y, acc);
        acc = fmaf(hn2, Ct4.z, acc);
        acc = fmaf(hn3, Ct4.w, acc);
    }
    acc += __shfl_xor_sync(0xffffffffu, acc, 1);
    acc += __shfl_xor_sync(0xffffffffu, acc, 2);
    if (l4 == 0) ys[tid >> 2] = fmaf(Dv[d], x_v, acc);
    __syncthreads();
    if (tid < 64) y[(size_t)b * DIN + dBase + tid] = ys[tid];
}

// ---------------- launch ----------------
extern "C" void kernel_launch(void* const* d_in, const int* in_sizes, int n_in,
                              void* d_out, int out_size) {
    const float* x      = (const float*)d_in[0];
    const float* h      = (const float*)d_in[1];
    const float* wdtlow = (const float*)d_in[2];
    const float* wdt    = (const float*)d_in[3];
    const float* bdt    = (const float*)d_in[4];
    const float* wb     = (const float*)d_in[5];
    const float* wc     = (const float*)d_in[6];
    const float* alog   = (const float*)d_in[7];
    const float* Dv     = (const float*)d_in[8];
    float* y = (float*)d_out;

    cudaFuncSetAttribute(gemm_wmma<0>, cudaFuncAttributeMaxDynamicSharedMemorySize, SMEM_DYN);
    cudaFuncSetAttribute(gemm_wmma<1>, cudaFuncAttributeMaxDynamicSharedMemorySize, SMEM_DYN);

    prep_all<<<PREP_BLOCKS, 256>>>(x, wdtlow, wb, wc, wdt, alog);
    gemm_wmma<0><<<dim3(B_SZ / 64, NPROJ / 64, SPLITK), 256, SMEM_DYN>>>(bdt);
    reduce_kernel<<<(B_SZ * NPROJ + 255) / 256, 256>>>();
    gemm_wmma<1><<<dim3(B_SZ / 64, DIN / 64, 1), 256, SMEM_DYN>>>(bdt);
    ssm_kernel<<<dim3(DIN / 64, B_SZ), 256>>>(x, h, Dv, y);
}

// round 12
// speedup vs baseline: 1.1953x; 1.1493x over previous
#include <cuda_runtime.h>
#include <cuda_fp16.h>
#include <mma.h>
#include <math.h>
#include <stdint.h>

using namespace nvcuda;

// 0: x [1024,2560]  1: h [1024,2560,16]  2: W_dt_low [160,2560]  3: W_dt [2560,160]
// 4: b_dt [2560]    5: W_B [16,2560]     6: W_C [16,2560]        7: A_log [2560,16]
// 8: D [2560]       out: y [1024,2560]   all f32

#define B_SZ    1024
#define DIN     2560
#define DST     16
#define DTR     160
#define NPROJ   192
#define KPAD    192
#define SPLITK  8
#define KSPLIT  (DIN / SPLITK)   // 320
#define KC      64               // 4 kk-steps per chunk
#define PADK    72

// ---------------- device scratch ----------------
__device__ __align__(16) __half g_xh[B_SZ * DIN], g_xl[B_SZ * DIN];   // x hi/lo (fp16)
__device__ __align__(16) __half g_w1[NPROJ * DIN];                    // W1 single fp16
__device__ __align__(16) __half g_w2[DIN * KPAD];                     // W2 single fp16 (padded)
__device__ __align__(16) __half g_ph[B_SZ * KPAD], g_pl[B_SZ * KPAD]; // proj hi/lo
__device__ __align__(16) float g_partial[SPLITK * B_SZ * NPROJ];
__device__ __align__(16) float g_proj[B_SZ * NPROJ];
__device__ __align__(16) float g_dt[B_SZ * DIN];
__device__ __align__(16) float g_A2[DIN * DST];

// ---------------- helpers ----------------
__device__ __forceinline__ void split2h(float v, __half& hi, __half& lo) {
    hi = __float2half_rn(v);
    lo = __float2half_rn(v - __half2float(hi));
}
__device__ __forceinline__ void split_store4h(float4 v, __half* ph, __half* pl) {
    __half h0, h1, h2, h3, l0, l1, l2, l3;
    split2h(v.x, h0, l0); split2h(v.y, h1, l1); split2h(v.z, h2, l2); split2h(v.w, h3, l3);
    reinterpret_cast<__half2*>(ph)[0] = __halves2half2(h0, h1);
    reinterpret_cast<__half2*>(ph)[1] = __halves2half2(h2, h3);
    reinterpret_cast<__half2*>(pl)[0] = __halves2half2(l0, l1);
    reinterpret_cast<__half2*>(pl)[1] = __halves2half2(l2, l3);
}
__device__ __forceinline__ void store4h(float4 v, __half* p) {
    reinterpret_cast<__half2*>(p)[0] = __halves2half2(__float2half_rn(v.x), __float2half_rn(v.y));
    reinterpret_cast<__half2*>(p)[1] = __halves2half2(__float2half_rn(v.z), __float2half_rn(v.w));
}
__device__ __forceinline__ void cp16(void* sdst, const void* gsrc) {
    asm volatile("cp.async.cg.shared.global [%0], [%1], 16;"
        :: "r"((uint32_t)__cvta_generic_to_shared(sdst)), "l"(gsrc));
}
#define CP_COMMIT() asm volatile("cp.async.commit_group;" ::: "memory")
#define CP_WAIT(N)  asm volatile("cp.async.wait_group %0;" :: "n"(N) : "memory")

// ---------------- fused prep ----------------
// [0,2560) conv_x (hi/lo); [2560,3040) conv_w1; [3040,3520) conv_w2; [3520,3560) prep_a
#define PREP_BLOCKS 3560
__global__ __launch_bounds__(256) void prep_all(const float* __restrict__ x,
                                                const float* __restrict__ wdtlow,
                                                const float* __restrict__ wb,
                                                const float* __restrict__ wc,
                                                const float* __restrict__ wdt,
                                                const float* __restrict__ alog) {
    const int bid = blockIdx.x;
    const int tid = threadIdx.x;
    if (bid < 2560) {
        int i = bid * 256 + tid;
        float4 v = reinterpret_cast<const float4*>(x)[i];
        split_store4h(v, g_xh + i * 4, g_xl + i * 4);
    } else if (bid < 3040) {
        int i = (bid - 2560) * 256 + tid;
        int n = i / (DIN / 4);
        int j = i % (DIN / 4);
        const float* row = (n < DTR) ? wdtlow + (size_t)n * DIN
                         : (n < DTR + DST) ? wb + (size_t)(n - DTR) * DIN
                         : wc + (size_t)(n - DTR - DST) * DIN;
        float4 v = reinterpret_cast<const float4*>(row)[j];
        store4h(v, g_w1 + i * 4);
    } else if (bid < 3520) {
        int i = (bid - 3040) * 256 + tid;
        int n = i / (KPAD / 4);
        int c4 = (i % (KPAD / 4)) * 4;
        float4 v = (c4 < DTR) ? *reinterpret_cast<const float4*>(wdt + (size_t)n * DTR + c4)
                              : make_float4(0.f, 0.f, 0.f, 0.f);
        store4h(v, g_w2 + (size_t)n * KPAD + c4);
    } else {
        int i = (bid - 3520) * 256 + tid;
        float4 v = reinterpret_cast<const float4*>(alog)[i];
        float4 o = make_float4(-__expf(v.x), -__expf(v.y), -__expf(v.z), -__expf(v.w));
        reinterpret_cast<float4*>(g_A2)[i] = o;
    }
}

// ---------------- wmma GEMM, 64m x 64n CTA, 8 warps (4x2), warp = 16m x 32n ----------------
// fp16, A split hi/lo (2 terms), B single. cp.async 2-stage; register-pipelined fragments.
// stage: sAh 9216 | sAl 9216 | sB 9216 = 27648; x2 = 55296
#define STAGE_SZ 27648
#define SMEM_DYN (2 * STAGE_SZ)

typedef wmma::fragment<wmma::matrix_a, 16, 16, 16, __half, wmma::row_major> FragA;
typedef wmma::fragment<wmma::matrix_b, 16, 16, 16, __half, wmma::col_major> FragB;
typedef wmma::fragment<wmma::accumulator, 16, 16, 16, float> FragC;

template<int MODE>
__global__ __launch_bounds__(256, 2) void gemm_wmma(const float* __restrict__ bias) {
    extern __shared__ __align__(16) char smbuf[];
    const int tid = threadIdx.x;
    const int wid = tid >> 5;
    const int wm = wid >> 1;
    const int wn = wid & 1;
    const int mBase = blockIdx.x * 64;
    const int nBase = blockIdx.y * 64;
    const int kOff  = (MODE == 0) ? blockIdx.z * KSPLIT : 0;
    const int nch   = ((MODE == 0) ? KSPLIT : KPAD) / KC;
    const int lda   = (MODE == 0) ? DIN : KPAD;
    const int ldb   = (MODE == 0) ? DIN : KPAD;
    const __half* aH = (MODE == 0) ? g_xh : g_ph;
    const __half* aL = (MODE == 0) ? g_xl : g_pl;
    const __half* bW = (MODE == 0) ? g_w1 : g_w2;

    auto prefetch = [&](int stage, int k0) {
        char* base = smbuf + stage * STAGE_SZ;
        __half* sAh = reinterpret_cast<__half*>(base);
        __half* sAl = reinterpret_cast<__half*>(base + 9216);
        __half* sB  = reinterpret_cast<__half*>(base + 18432);
#pragma unroll
        for (int s = 0; s < 2; s++) {
            int u = tid + s * 256;
            int row = u >> 3, c16 = u & 7;
            const size_t goa = (size_t)(mBase + row) * lda + k0 + c16 * 8;
            const size_t gob = (size_t)(nBase + row) * ldb + k0 + c16 * 8;
            cp16(sAh + row * PADK + c16 * 8, aH + goa);
            cp16(sAl + row * PADK + c16 * 8, aL + goa);
            cp16(sB  + row * PADK + c16 * 8, bW + gob);
        }
        CP_COMMIT();
    };

    FragC acc0[2], acc1[2];
#pragma unroll
    for (int j = 0; j < 2; j++) { wmma::fill_fragment(acc0[j], 0.0f); wmma::fill_fragment(acc1[j], 0.0f); }

    prefetch(0, kOff);

    FragA ah[2], al[2];
    FragB bf[2][2];

    for (int ch = 0; ch < nch; ch++) {
        const int stage = ch & 1;
        if (ch + 1 < nch) {
            prefetch(stage ^ 1, kOff + (ch + 1) * KC);
            CP_WAIT(1);
        } else {
            CP_WAIT(0);
        }
        __syncthreads();

        char* base = smbuf + stage * STAGE_SZ;
        __half* sAh = reinterpret_cast<__half*>(base);
        __half* sAl = reinterpret_cast<__half*>(base + 9216);
        __half* sB  = reinterpret_cast<__half*>(base + 18432);

        // kk=0 fragments into buffer 0
        wmma::load_matrix_sync(ah[0], sAh + (wm * 16) * PADK, PADK);
        wmma::load_matrix_sync(al[0], sAl + (wm * 16) * PADK, PADK);
#pragma unroll
        for (int j = 0; j < 2; j++)
            wmma::load_matrix_sync(bf[0][j], sB + (wn * 32 + j * 16) * PADK, PADK);

#pragma unroll
        for (int kk = 0; kk < 4; kk++) {
            const int cur = kk & 1, nxt = cur ^ 1;
            if (kk < 3) {
                wmma::load_matrix_sync(ah[nxt], sAh + (wm * 16) * PADK + (kk + 1) * 16, PADK);
                wmma::load_matrix_sync(al[nxt], sAl + (wm * 16) * PADK + (kk + 1) * 16, PADK);
#pragma unroll
                for (int j = 0; j < 2; j++)
                    wmma::load_matrix_sync(bf[nxt][j], sB + (wn * 32 + j * 16) * PADK + (kk + 1) * 16, PADK);
            }
            // 4 independent MMAs
            wmma::mma_sync(acc0[0], ah[cur], bf[cur][0], acc0[0]);
            wmma::mma_sync(acc0[1], ah[cur], bf[cur][1], acc0[1]);
            wmma::mma_sync(acc1[0], al[cur], bf[cur][0], acc1[0]);
            wmma::mma_sync(acc1[1], al[cur], bf[cur][1], acc1[1]);
        }
        __syncthreads();
    }

    FragC acc[2];
#pragma unroll
    for (int j = 0; j < 2; j++) {
#pragma unroll
        for (int e = 0; e < acc[j].num_elements; e++)
            acc[j].x[e] = acc0[j].x[e] + acc1[j].x[e];
    }

    if (MODE == 0) {
        float* base = g_partial + ((size_t)blockIdx.z * B_SZ + mBase) * NPROJ + nBase;
#pragma unroll
        for (int j = 0; j < 2; j++) {
            float* p = base + (size_t)(wm * 16) * NPROJ + wn * 32 + j * 16;
            wmma::store_matrix_sync(p, acc[j], NPROJ, wmma::mem_row_major);
        }
    } else {
        float* stage = reinterpret_cast<float*>(smbuf);   // 64 x 68 f32 = 17408B
#pragma unroll
        for (int j = 0; j < 2; j++) {
            float* p = stage + (size_t)(wm * 16) * 68 + wn * 32 + j * 16;
            wmma::store_matrix_sync(p, acc[j], 68, wmma::mem_row_major);
        }
        __syncthreads();
#pragma unroll
        for (int s = 0; s < 4; s++) {
            int u = tid + s * 256;
            int row = u >> 4, c4 = (u & 15) * 4;
            float4 v = *reinterpret_cast<float4*>(stage + row * 68 + c4);
            const int gn = nBase + c4;
            v.x += __ldg(bias + gn);     v.y += __ldg(bias + gn + 1);
            v.z += __ldg(bias + gn + 2); v.w += __ldg(bias + gn + 3);
            float4 o;
            o.x = fmaxf(v.x, 0.f) + log1pf(__expf(-fabsf(v.x)));
            o.y = fmaxf(v.y, 0.f) + log1pf(__expf(-fabsf(v.y)));
            o.z = fmaxf(v.z, 0.f) + log1pf(__expf(-fabsf(v.z)));
            o.w = fmaxf(v.w, 0.f) + log1pf(__expf(-fabsf(v.w)));
            *reinterpret_cast<float4*>(g_dt + (size_t)(mBase + row) * DIN + gn) = o;
        }
    }
}

// ---------------- split-K reduce + fp16 split of proj ----------------
__global__ void reduce_kernel() {
    int i = blockIdx.x * blockDim.x + threadIdx.x;
    const int total = B_SZ * NPROJ;
    if (i >= total) return;
    float s = g_partial[i];
#pragma unroll
    for (int z = 1; z < SPLITK; z++) s += g_partial[(size_t)z * total + i];
    g_proj[i] = s;
    __half hi, lo;
    split2h(s, hi, lo);
    g_ph[i] = hi; g_pl[i] = lo;
}

// ---------------- elementwise SSM ----------------
__global__ __launch_bounds__(256) void ssm_kernel(const float* __restrict__ x,
                                                  const float* __restrict__ h,
                                                  const float* __restrict__ Dv,
                                                  float* __restrict__ y) {
    __shared__ float ys[64];
    const int b = blockIdx.y;
    const int dBase = blockIdx.x * 64;
    const int tid = threadIdx.x;
    const int l4 = tid & 3;
    const int d = dBase + (tid >> 2);
    const int pair = b * DIN + d;

    const float dt_v = g_dt[pair];
    const float x_v = x[pair];
    const float4 h4  = *reinterpret_cast<const float4*>(h + (size_t)pair * DST + l4 * 4);
    const float4 A4  = *reinterpret_cast<const float4*>(g_A2 + (size_t)d * DST + l4 * 4);
    const float4 Bt4 = *reinterpret_cast<const float4*>(g_proj + (size_t)b * NPROJ + DTR + l4 * 4);
    const float4 Ct4 = *reinterpret_cast<const float4*>(g_proj + (size_t)b * NPROJ + DTR + DST + l4 * 4);

    const float dx = dt_v * x_v;
    float acc;
    {
        float e0 = __expf(dt_v * A4.x);
        float e1 = __expf(dt_v * A4.y);
        float e2 = __expf(dt_v * A4.z);
        float e3 = __expf(dt_v * A4.w);
        float hn0 = fmaf(e0, h4.x, dx * Bt4.x);
        float hn1 = fmaf(e1, h4.y, dx * Bt4.y);
        float hn2 = fmaf(e2, h4.z, dx * Bt4.z);
        float hn3 = fmaf(e3, h4.w, dx * Bt4.w);
        acc = hn0 * Ct4.x;
        acc = fmaf(hn1, Ct4.y, acc);
        acc = fmaf(hn2, Ct4.z, acc);
        acc = fmaf(hn3, Ct4.w, acc);
    }
    acc += __shfl_xor_sync(0xffffffffu, acc, 1);
    acc += __shfl_xor_sync(0xffffffffu, acc, 2);
    if (l4 == 0) ys[tid >> 2] = fmaf(Dv[d], x_v, acc);
    __syncthreads();
    if (tid < 64) y[(size_t)b * DIN + dBase + tid] = ys[tid];
}

// ---------------- launch ----------------
extern "C" void kernel_launch(void* const* d_in, const int* in_sizes, int n_in,
                              void* d_out, int out_size) {
    const float* x      = (const float*)d_in[0];
    const float* h      = (const float*)d_in[1];
    const float* wdtlow = (const float*)d_in[2];
    const float* wdt    = (const float*)d_in[3];
    const float* bdt    = (const float*)d_in[4];
    const float* wb     = (const float*)d_in[5];
    const float* wc     = (const float*)d_in[6];
    const float* alog   = (const float*)d_in[7];
    const float* Dv     = (const float*)d_in[8];
    float* y = (float*)d_out;

    cudaFuncSetAttribute(gemm_wmma<0>, cudaFuncAttributeMaxDynamicSharedMemorySize, SMEM_DYN);
    cudaFuncSetAttribute(gemm_wmma<1>, cudaFuncAttributeMaxDynamicSharedMemorySize, SMEM_DYN);

    prep_all<<<PREP_BLOCKS, 256>>>(x, wdtlow, wb, wc, wdt, alog);
    gemm_wmma<0><<<dim3(B_SZ / 64, NPROJ / 64, SPLITK), 256, SMEM_DYN>>>(bdt);
    reduce_kernel<<<(B_SZ * NPROJ + 255) / 256, 256>>>();
    gemm_wmma<1><<<dim3(B_SZ / 64, DIN / 64, 1), 256, SMEM_DYN>>>(bdt);
    ssm_kernel<<<dim3(DIN / 64, B_SZ), 256>>>(x, h, Dv, y);
}